// round 8
// baseline (speedup 1.0000x reference)
#include <cuda_runtime.h>
#include <cuda_fp16.h>
#include <math.h>
#include <stdint.h>

// Problem constants
#define NE  160     // experts
#define CAP 120     // capacity per expert
#define NS  3200    // sequence length
#define NH  2048    // hidden dim
#define NI  192     // ffn dim per device
#define NK  6       // top-k

// fp16 scratch (halves inter-kernel HBM traffic)
__device__ __half g_h[(size_t)NE * CAP * NI];   // 7.4 MB
__device__ __half g_o[(size_t)NE * CAP * NH];   // 79  MB

// Row pitch in fp16 smem tiles: 40 halves = 80 bytes. 80 = 16*5 (16B aligned
// rows) and bank base 20*r mod 32 cycles {0,20,8,28,16,4,24,12} -> the 8 rows
// of an ldmatrix tile cover all 32 banks exactly once: conflict-free.
#define PITCH 80

// ---------------------------------------------------------------------------
// helpers
// ---------------------------------------------------------------------------
__device__ __forceinline__ uint32_t s2u(const void* p) {
    uint32_t a;
    asm("{ .reg .u64 t; cvta.to.shared.u64 t, %1; cvt.u32.u64 %0, t; }" : "=r"(a) : "l"(p));
    return a;
}
__device__ __forceinline__ void cp16s(uint32_t sa, const void* g) {
    asm volatile("cp.async.ca.shared.global [%0], [%1], 16;" :: "r"(sa), "l"(g));
}
__device__ __forceinline__ uint32_t pkf(float lo, float hi) {
    uint32_t r;
    asm("cvt.rn.f16x2.f32 %0, %1, %2;" : "=r"(r) : "f"(hi), "f"(lo));
    return r;
}
__device__ __forceinline__ void ldm_x4(uint32_t* r, uint32_t a) {
    asm volatile("ldmatrix.sync.aligned.m8n8.x4.shared.b16 {%0,%1,%2,%3}, [%4];"
                 : "=r"(r[0]), "=r"(r[1]), "=r"(r[2]), "=r"(r[3]) : "r"(a));
}
__device__ __forceinline__ void ldm_x2(uint32_t* r, uint32_t a) {
    asm volatile("ldmatrix.sync.aligned.m8n8.x2.shared.b16 {%0,%1}, [%2];"
                 : "=r"(r[0]), "=r"(r[1]) : "r"(a));
}
__device__ __forceinline__ void mma_f16(float* c, const uint32_t* a, const uint32_t* b) {
    asm volatile(
        "mma.sync.aligned.m16n8k16.row.col.f32.f16.f16.f32 "
        "{%0,%1,%2,%3},{%4,%5,%6,%7},{%8,%9},{%0,%1,%2,%3};"
        : "+f"(c[0]), "+f"(c[1]), "+f"(c[2]), "+f"(c[3])
        : "r"(a[0]), "r"(a[1]), "r"(a[2]), "r"(a[3]), "r"(b[0]), "r"(b[1]));
}
__device__ __forceinline__ float silu(float g) { return g / (1.f + __expf(-g)); }

// ---------------------------------------------------------------------------
// Kernel 1: gathered gate/up GEMM, fp16 smem + ldmatrix, fused SiLU
//   grid = (4 I-tiles of 48, NE), block = 256 (8 warps: wm 0..3 x wn 0..1)
//   K chunk 32 (2 k16 steps). LDG fp32 -> cvt -> STS fp16, 1 sync/chunk,
//   LDG issued one chunk ahead of its STS.
// ---------------------------------------------------------------------------
__global__ __launch_bounds__(256, 2) void k_gateup(
    const float* __restrict__ hs,   // [S,H]
    const int*   __restrict__ tok,  // [E,CAP]
    const float* __restrict__ gw,   // [E,I,H]
    const float* __restrict__ uw)   // [E,I,H]
{
    extern __shared__ __align__(16) char smem[];
    int* toks = (int*)smem;
    const uint32_t sb = s2u(smem);
    const uint32_t sA = sb + 512;            // [2][128*PITCH] = 20480
    const uint32_t sG = sA + 20480;          // [2][48*PITCH]  = 7680
    const uint32_t sU = sG + 7680;           // [2][48*PITCH]  = 7680

    const int e   = blockIdx.y;
    const int i0  = blockIdx.x * 48;
    const int tid = threadIdx.x;
    const int w   = tid >> 5, lane = tid & 31;
    const int wm  = w >> 1, wn = w & 1;
    const int lrow = lane & 7, lsel = lane >> 3;

    if (tid < 128) toks[tid] = tok[e * CAP + (tid < CAP ? tid : CAP - 1)];
    __syncthreads();

    // fixed per-thread global pointers + smem byte offsets (within buffer)
    const float* aptr[4]; uint32_t offA[4];
    const float* bptr[3]; uint32_t offB[3]; int isUp[3];
#pragma unroll
    for (int p = 0; p < 4; p++) {
        int idx = tid + p * 256;                       // A: [128][8 x f4]
        aptr[p] = hs + (size_t)toks[idx >> 3] * NH + (idx & 7) * 4;
        offA[p] = (uint32_t)((idx >> 3) * PITCH + (idx & 7) * 8);
    }
    {
        const float* gwe = gw + ((size_t)e * NI + i0) * NH;
        const float* uwe = uw + ((size_t)e * NI + i0) * NH;
#pragma unroll
        for (int p = 0; p < 3; p++) {
            int idx = tid + p * 256;                   // 768 = gate 384 + up 384
            int j = (idx < 384) ? idx : idx - 384;
            isUp[p] = (idx >= 384);
            bptr[p] = (idx < 384 ? gwe : uwe) + (size_t)(j >> 3) * NH + (j & 7) * 4;
            offB[p] = (uint32_t)((j >> 3) * PITCH + (j & 7) * 8);
        }
    }

    uint32_t RA[8], RB[6];
    auto ldg_chunk = [&](int k0) {
#pragma unroll
        for (int p = 0; p < 4; p++) {
            float4 v = *(const float4*)(aptr[p] + k0);
            RA[2*p]   = pkf(v.x, v.y);
            RA[2*p+1] = pkf(v.z, v.w);
        }
#pragma unroll
        for (int p = 0; p < 3; p++) {
            float4 v = *(const float4*)(bptr[p] + k0);
            RB[2*p]   = pkf(v.x, v.y);
            RB[2*p+1] = pkf(v.z, v.w);
        }
    };
    auto sts_chunk = [&](int buf) {
#pragma unroll
        for (int p = 0; p < 4; p++)
            *(uint2*)(smem + 512 + buf * 10240 + offA[p]) = make_uint2(RA[2*p], RA[2*p+1]);
#pragma unroll
        for (int p = 0; p < 3; p++) {
            char* base = smem + (isUp[p] ? 28672 : 20992) + buf * 3840;   // sG/sU - sb + 512? see note
            *(uint2*)(base + offB[p]) = make_uint2(RB[2*p], RB[2*p+1]);
        }
    };
    // note: sA = smem+512, sG = smem+20992, sU = smem+28672 (byte views)

    // ldmatrix lane offsets (bytes, within one buffer)
    const uint32_t aoff  = (uint32_t)((wm * 32 + lrow + ((lsel & 1) << 3)) * PITCH + ((lsel >> 1) << 4));
    const uint32_t boff4 = (uint32_t)((wn * 24 + lrow + ((lsel >> 1) << 3)) * PITCH + ((lsel & 1) << 4));
    const uint32_t boff2 = (uint32_t)((wn * 24 + 16 + lrow) * PITCH + ((lsel & 1) << 4));

    float accg[2][3][4] = {};
    float accu[2][3][4] = {};

    const int NC = NH / 32;        // 64 chunks
    ldg_chunk(0);
    sts_chunk(0);
    ldg_chunk(32);
    __syncthreads();

    for (int kc = 0; kc < NC; kc++) {
        const int buf = kc & 1;
        const uint32_t Ab = sA + buf * 10240;
        const uint32_t Gb = sG + buf * 3840;
        const uint32_t Ub = sU + buf * 3840;
#pragma unroll
        for (int ks = 0; ks < 2; ks++) {
            const uint32_t kb = ks * 32;
            uint32_t a0[4], a1[4], b4[4], b2[2];
            ldm_x4(a0, Ab + aoff + kb);
            ldm_x4(a1, Ab + aoff + 16 * PITCH + kb);
            ldm_x4(b4, Gb + boff4 + kb);
            ldm_x2(b2, Gb + boff2 + kb);
            mma_f16(accg[0][0], a0, b4);     mma_f16(accg[1][0], a1, b4);
            mma_f16(accg[0][1], a0, b4 + 2); mma_f16(accg[1][1], a1, b4 + 2);
            mma_f16(accg[0][2], a0, b2);     mma_f16(accg[1][2], a1, b2);
            ldm_x4(b4, Ub + boff4 + kb);
            ldm_x2(b2, Ub + boff2 + kb);
            mma_f16(accu[0][0], a0, b4);     mma_f16(accu[1][0], a1, b4);
            mma_f16(accu[0][1], a0, b4 + 2); mma_f16(accu[1][1], a1, b4 + 2);
            mma_f16(accu[0][2], a0, b2);     mma_f16(accu[1][2], a1, b2);
        }
        if (kc + 1 < NC) {
            sts_chunk(buf ^ 1);                    // safe: buf^1 last read at kc-1
            if (kc + 2 < NC) ldg_chunk((kc + 2) * 32);
            __syncthreads();
        }
    }

    // Epilogue: h = silu(g)*u -> g_h (fp16)
    const int gr = lane >> 2, tg = lane & 3;
#pragma unroll
    for (int mt = 0; mt < 2; mt++) {
#pragma unroll
        for (int half = 0; half < 2; half++) {
            const int r = wm * 32 + mt * 16 + gr + half * 8;
            if (r < CAP) {
                __half* dst = g_h + ((size_t)e * CAP + r) * NI + i0 + wn * 24;
#pragma unroll
                for (int nt = 0; nt < 3; nt++) {
                    float g0 = accg[mt][nt][half * 2 + 0];
                    float g1 = accg[mt][nt][half * 2 + 1];
                    float u0 = accu[mt][nt][half * 2 + 0];
                    float u1 = accu[mt][nt][half * 2 + 1];
                    *(__half2*)(dst + nt * 8 + 2 * tg) =
                        __floats2half2_rn(silu(g0) * u0, silu(g1) * u1);
                }
            }
        }
    }
}

// ---------------------------------------------------------------------------
// Kernel 2: down projection, fp16 smem + ldmatrix
//   grid = (16 H-tiles of 128, NE). Block tile M=128 N=128 K=192.
//   A (g_h, already fp16) fully resident: 6 chunk-tiles via cp.async.
//   B: LDG fp32 -> cvt -> STS fp16, double-buffered.
// ---------------------------------------------------------------------------
__global__ __launch_bounds__(256, 2) void k_down(const float* __restrict__ dw /*[E,H,I]*/)
{
    extern __shared__ __align__(16) char smem[];
    const uint32_t sb = s2u(smem);
    const uint32_t sA = sb;                  // 6 x 10240 = 61440
    const uint32_t sB = sb + 61440;          // 2 x 10240 = 20480

    const int e   = blockIdx.y;
    const int h0  = blockIdx.x * 128;
    const int tid = threadIdx.x;
    const int w   = tid >> 5, lane = tid & 31;
    const int wm  = w >> 1, wn = w & 1;
    const int lrow = lane & 7, lsel = lane >> 3;

    // Preload whole A: [6][128][4 x 16B] fp16 from g_h
    const __half* hsrc = g_h + (size_t)e * CAP * NI;
#pragma unroll
    for (int p = 0; p < 12; p++) {
        int idx = tid + p * 256;             // 3072 total
        int kc = idx >> 9, rem = idx & 511, r = rem >> 2, c = rem & 3;
        int rr = r < CAP ? r : CAP - 1;
        cp16s(sA + kc * 10240 + r * PITCH + c * 16,
              hsrc + (size_t)rr * NI + kc * 32 + c * 8);
    }
    asm volatile("cp.async.commit_group;");

    // B fixed pointers: [128][8 x f4] per chunk
    const float* dwe = dw + ((size_t)e * NH + h0) * NI;
    const float* bptr[4]; uint32_t offB[4];
#pragma unroll
    for (int p = 0; p < 4; p++) {
        int idx = tid + p * 256;
        bptr[p] = dwe + (size_t)(idx >> 3) * NI + (idx & 7) * 4;
        offB[p] = (uint32_t)((idx >> 3) * PITCH + (idx & 7) * 8);
    }

    uint32_t RB[8];
    auto ldg_chunk = [&](int k0) {
#pragma unroll
        for (int p = 0; p < 4; p++) {
            float4 v = *(const float4*)(bptr[p] + k0);
            RB[2*p]   = pkf(v.x, v.y);
            RB[2*p+1] = pkf(v.z, v.w);
        }
    };
    auto sts_chunk = [&](int buf) {
#pragma unroll
        for (int p = 0; p < 4; p++)
            *(uint2*)(smem + 61440 + buf * 10240 + offB[p]) = make_uint2(RB[2*p], RB[2*p+1]);
    };

    const uint32_t aoff  = (uint32_t)((wm * 32 + lrow + ((lsel & 1) << 3)) * PITCH + ((lsel >> 1) << 4));
    const uint32_t boff4 = (uint32_t)((lrow + ((lsel >> 1) << 3)) * PITCH + ((lsel & 1) << 4));

    float acc[2][8][4] = {};

    ldg_chunk(0);
    sts_chunk(0);
    ldg_chunk(32);
    asm volatile("cp.async.wait_group 0;");
    __syncthreads();

    for (int kc = 0; kc < 6; kc++) {
        const int buf = kc & 1;
        const uint32_t Ab = sA + kc * 10240;
        const uint32_t Bb = sB + buf * 10240;
#pragma unroll
        for (int ks = 0; ks < 2; ks++) {
            const uint32_t kb = ks * 32;
            uint32_t a0[4], a1[4];
            ldm_x4(a0, Ab + aoff + kb);
            ldm_x4(a1, Ab + aoff + 16 * PITCH + kb);
#pragma unroll
            for (int pr = 0; pr < 4; pr++) {     // nt pairs
                uint32_t b4[4];
                ldm_x4(b4, Bb + boff4 + (uint32_t)((wn * 64 + pr * 16) * PITCH) + kb);
                mma_f16(acc[0][2*pr],     a0, b4);     mma_f16(acc[1][2*pr],     a1, b4);
                mma_f16(acc[0][2*pr + 1], a0, b4 + 2); mma_f16(acc[1][2*pr + 1], a1, b4 + 2);
            }
        }
        if (kc + 1 < 6) {
            sts_chunk(buf ^ 1);
            if (kc + 2 < 6) ldg_chunk((kc + 2) * 32);
            __syncthreads();
        }
    }

    // Epilogue -> g_o (fp16)
    const int gr = lane >> 2, tg = lane & 3;
#pragma unroll
    for (int mt = 0; mt < 2; mt++) {
#pragma unroll
        for (int half = 0; half < 2; half++) {
            const int r = wm * 32 + mt * 16 + gr + half * 8;
            if (r < CAP) {
                __half* dst = g_o + ((size_t)e * CAP + r) * NH + h0 + wn * 64;
#pragma unroll
                for (int nt = 0; nt < 8; nt++) {
                    *(__half2*)(dst + nt * 8 + 2 * tg) =
                        __floats2half2_rn(acc[mt][nt][half * 2 + 0],
                                          acc[mt][nt][half * 2 + 1]);
                }
            }
        }
    }
}

// ---------------------------------------------------------------------------
// Kernel 3: permute-gather + top-k weighted combine + shared expert
// ---------------------------------------------------------------------------
__global__ __launch_bounds__(256) void k_combine(
    const int*   __restrict__ rei,  // [K*S]
    const float* __restrict__ tw,   // [K,S,1]
    const float* __restrict__ sh,   // [1,S,H]
    float*       __restrict__ out)  // [1,S,H]
{
    const int s = blockIdx.x;
    __shared__ int   rows[NK];
    __shared__ float wts[NK];
    if (threadIdx.x < NK) {
        rows[threadIdx.x] = rei[threadIdx.x * NS + s];
        wts[threadIdx.x]  = tw[threadIdx.x * NS + s];
    }
    __syncthreads();

    for (int h = threadIdx.x * 4; h < NH; h += 256 * 4) {
        float4 a = *(const float4*)(sh + (size_t)s * NH + h);
#pragma unroll
        for (int k = 0; k < NK; k++) {
            const __half* src = g_o + (size_t)rows[k] * NH + h;
            float2 f01 = __half22float2(*(const __half2*)(src));
            float2 f23 = __half22float2(*(const __half2*)(src + 2));
            const float wv = wts[k];
            a.x = fmaf(wv, f01.x, a.x);
            a.y = fmaf(wv, f01.y, a.y);
            a.z = fmaf(wv, f23.x, a.z);
            a.w = fmaf(wv, f23.y, a.w);
        }
        *(float4*)(out + (size_t)s * NH + h) = a;
    }
}

// ---------------------------------------------------------------------------
extern "C" void kernel_launch(void* const* d_in, const int* in_sizes, int n_in,
                              void* d_out, int out_size)
{
    const float* hs  = (const float*)d_in[0];
    const int*   tok = (const int*)  d_in[1];
    const int*   rei = (const int*)  d_in[2];
    const float* tw  = (const float*)d_in[3];
    const float* sh  = (const float*)d_in[4];
    const float* gw  = (const float*)d_in[5];
    const float* uw  = (const float*)d_in[6];
    const float* dw  = (const float*)d_in[7];
    float* out = (float*)d_out;

    const int smem1 = 512 + 2 * 10240 + 2 * 3840 + 2 * 3840;   // 36352 B
    const int smem2 = 6 * 10240 + 2 * 10240;                   // 81920 B
    cudaFuncSetAttribute(k_gateup, cudaFuncAttributeMaxDynamicSharedMemorySize, smem1);
    cudaFuncSetAttribute(k_down,   cudaFuncAttributeMaxDynamicSharedMemorySize, smem2);

    dim3 g1(4, NE);         // 640 blocks
    k_gateup<<<g1, 256, smem1>>>(hs, tok, gw, uw);

    dim3 g2(NH / 128, NE);  // 2560 blocks
    k_down<<<g2, 256, smem2>>>(dw);

    k_combine<<<NS, 256>>>(rei, tw, sh, out);
}

// round 11
// speedup vs baseline: 1.0912x; 1.0912x over previous
#include <cuda_runtime.h>
#include <cuda_fp16.h>
#include <math.h>
#include <stdint.h>

// Problem constants
#define NE  160     // experts
#define CAP 120     // capacity per expert
#define NS  3200    // sequence length
#define NH  2048    // hidden dim
#define NI  192     // ffn dim per device
#define NK  6       // top-k

#define P   40      // fp32 smem pitch (floats); LDS.64 frag loads conflict-free
#define PB  80      // fp16 smem pitch (bytes) for down's resident A

// fp16 scratch (halves inter-kernel HBM traffic)
__device__ __half g_h[(size_t)NE * CAP * NI];   // 7.4 MB
__device__ __half g_o[(size_t)NE * CAP * NH];   // 79  MB

// single dynamic-shared symbol, cast per-kernel
extern __shared__ __align__(16) char dynsmem[];

// ---------------------------------------------------------------------------
// helpers
// ---------------------------------------------------------------------------
__device__ __forceinline__ uint32_t s2u(const void* p) {
    uint32_t a;
    asm("{ .reg .u64 t; cvta.to.shared.u64 t, %1; cvt.u32.u64 %0, t; }" : "=r"(a) : "l"(p));
    return a;
}
__device__ __forceinline__ void cp16(float* smem_dst, const float* gsrc) {
    uint32_t sa = (uint32_t)__cvta_generic_to_shared(smem_dst);
    asm volatile("cp.async.ca.shared.global [%0], [%1], 16;" :: "r"(sa), "l"(gsrc));
}
__device__ __forceinline__ void cp16s(uint32_t sa, const void* g) {
    asm volatile("cp.async.ca.shared.global [%0], [%1], 16;" :: "r"(sa), "l"(g));
}
__device__ __forceinline__ void cp_commit() { asm volatile("cp.async.commit_group;"); }
template<int N> __device__ __forceinline__ void cp_wait() {
    asm volatile("cp.async.wait_group %0;" :: "n"(N));
}
// pack float2 {lo,hi} -> f16x2 (lo in low 16 bits)
__device__ __forceinline__ uint32_t pk(float2 v) {
    uint32_t r;
    asm("cvt.rn.f16x2.f32 %0, %1, %2;" : "=r"(r) : "f"(v.y), "f"(v.x));
    return r;
}
__device__ __forceinline__ void ldm_x4(uint32_t* r, uint32_t a) {
    asm volatile("ldmatrix.sync.aligned.m8n8.x4.shared.b16 {%0,%1,%2,%3}, [%4];"
                 : "=r"(r[0]), "=r"(r[1]), "=r"(r[2]), "=r"(r[3]) : "r"(a));
}
__device__ __forceinline__ void mma_f16(float* c, const uint32_t* a, const uint32_t* b) {
    asm volatile(
        "mma.sync.aligned.m16n8k16.row.col.f32.f16.f16.f32 "
        "{%0,%1,%2,%3},{%4,%5,%6,%7},{%8,%9},{%0,%1,%2,%3};"
        : "+f"(c[0]), "+f"(c[1]), "+f"(c[2]), "+f"(c[3])
        : "r"(a[0]), "r"(a[1]), "r"(a[2]), "r"(a[3]), "r"(b[0]), "r"(b[1]));
}
__device__ __forceinline__ float silu(float g) { return g / (1.f + __expf(-g)); }
__device__ __forceinline__ float2 ld2(const float* p) { return *(const float2*)p; }

// ---------------------------------------------------------------------------
// Kernel 1: gathered gate/up GEMM (fp16 MMA, fp32 accum) + fused SiLU
//   grid = (2 I-halves of 96, NE) = 320 blocks. 256 thr, 8 warps (wm4 x wn2).
//   Block tile M=128 x N=96 for BOTH gate and up; warp tile 32x48 per matrix.
//   K chunk 32 (2 k16 steps), 2-stage cp.async (fp32 smem), frag pack to fp16.
//   A loaded 2x/expert (vs 4x at N=48) -> less crossbar + HBM.
// ---------------------------------------------------------------------------
__global__ __launch_bounds__(256) void k_gateup(
    const float* __restrict__ hs,   // [S,H]
    const int*   __restrict__ tok,  // [E,CAP]
    const float* __restrict__ gw,   // [E,I,H]
    const float* __restrict__ uw)   // [E,I,H]
{
    float* smem = (float*)dynsmem;
    float* As = smem;               // [2][128*P]
    float* Bg = As + 2 * 128 * P;   // [2][96*P]
    float* Bu = Bg + 2 * 96 * P;    // [2][96*P]

    const int e   = blockIdx.y;
    const int i0  = blockIdx.x * 96;
    const int tid = threadIdx.x;
    const int w   = tid >> 5, lane = tid & 31;
    const int wm  = w >> 1, wn = w & 1;
    const int gr  = lane >> 2, tg = lane & 3;

    __shared__ int toks[128];
    if (tid < CAP)      toks[tid] = tok[e * CAP + tid];
    else if (tid < 128) toks[tid] = tok[e * CAP + CAP - 1];
    __syncthreads();

    const float* gwe = gw + ((size_t)e * NI + i0) * NH;
    const float* uwe = uw + ((size_t)e * NI + i0) * NH;

    float accg[2][6][4] = {};
    float accu[2][6][4] = {};

    const int NC = NH / 32;        // 64 chunks

    auto load_chunk = [&](int buf, int kc) {
        const int k0 = kc * 32;
        float* Ab = As + buf * 128 * P;
        float* Gb = Bg + buf * 96 * P;
        float* Ub = Bu + buf * 96 * P;
#pragma unroll
        for (int p = 0; p < 4; p++) {           // A: 128 rows x 8 f4
            int idx = tid + p * 256;
            int r = idx >> 3, c4 = (idx & 7) << 2;
            cp16(Ab + r * P + c4, hs + (size_t)toks[r] * NH + k0 + c4);
        }
#pragma unroll
        for (int p = 0; p < 3; p++) {           // Bg: 96 x 8 f4
            int idx = tid + p * 256;
            int r = idx >> 3, c4 = (idx & 7) << 2;
            cp16(Gb + r * P + c4, gwe + (size_t)r * NH + k0 + c4);
        }
#pragma unroll
        for (int p = 0; p < 3; p++) {           // Bu: 96 x 8 f4
            int idx = tid + p * 256;
            int r = idx >> 3, c4 = (idx & 7) << 2;
            cp16(Ub + r * P + c4, uwe + (size_t)r * NH + k0 + c4);
        }
    };

    load_chunk(0, 0);
    cp_commit();

    int buf = 0;
    for (int kc = 0; kc < NC; kc++) {
        if (kc + 1 < NC) {
            load_chunk(buf ^ 1, kc + 1);
            cp_commit();
            cp_wait<1>();
        } else {
            cp_wait<0>();
        }
        __syncthreads();

        const float* A  = As + buf * 128 * P + wm * 32 * P;
        const float* BG = Bg + buf * 96 * P + wn * 48 * P;
        const float* BU = Bu + buf * 96 * P + wn * 48 * P;

#pragma unroll
        for (int ks = 0; ks < 2; ks++) {
            const int c0 = ks * 16 + 2 * tg;
            uint32_t a0[4], a1[4];
            a0[0] = pk(ld2(&A[(gr     ) * P + c0    ]));
            a0[1] = pk(ld2(&A[(gr +  8) * P + c0    ]));
            a0[2] = pk(ld2(&A[(gr     ) * P + c0 + 8]));
            a0[3] = pk(ld2(&A[(gr +  8) * P + c0 + 8]));
            a1[0] = pk(ld2(&A[(gr + 16) * P + c0    ]));
            a1[1] = pk(ld2(&A[(gr + 24) * P + c0    ]));
            a1[2] = pk(ld2(&A[(gr + 16) * P + c0 + 8]));
            a1[3] = pk(ld2(&A[(gr + 24) * P + c0 + 8]));
#pragma unroll
            for (int nt = 0; nt < 6; nt++) {
                uint32_t b[2];
                b[0] = pk(ld2(&BG[(nt * 8 + gr) * P + c0    ]));
                b[1] = pk(ld2(&BG[(nt * 8 + gr) * P + c0 + 8]));
                mma_f16(accg[0][nt], a0, b);
                mma_f16(accg[1][nt], a1, b);
                b[0] = pk(ld2(&BU[(nt * 8 + gr) * P + c0    ]));
                b[1] = pk(ld2(&BU[(nt * 8 + gr) * P + c0 + 8]));
                mma_f16(accu[0][nt], a0, b);
                mma_f16(accu[1][nt], a1, b);
            }
        }
        __syncthreads();
        buf ^= 1;
    }

    // Epilogue: h = silu(g)*u -> g_h (fp16)
#pragma unroll
    for (int mt = 0; mt < 2; mt++) {
#pragma unroll
        for (int half = 0; half < 2; half++) {
            const int r = wm * 32 + mt * 16 + gr + half * 8;
            if (r < CAP) {
                __half* dst = g_h + ((size_t)e * CAP + r) * NI + i0 + wn * 48;
#pragma unroll
                for (int nt = 0; nt < 6; nt++) {
                    float g0 = accg[mt][nt][half * 2 + 0];
                    float g1 = accg[mt][nt][half * 2 + 1];
                    float u0 = accu[mt][nt][half * 2 + 0];
                    float u1 = accu[mt][nt][half * 2 + 1];
                    *(__half2*)(dst + nt * 8 + 2 * tg) =
                        __floats2half2_rn(silu(g0) * u0, silu(g1) * u1);
                }
            }
        }
    }
}

// ---------------------------------------------------------------------------
// Kernel 2: down projection. A resident fp16 (ldmatrix), B streamed fp32
//   via cp.async + fragment pack. grid (16 H-tiles of 128, NE), 256 thr.
//   Block tile M=128 x N=128, K=192; warp 32x64.
// ---------------------------------------------------------------------------
__global__ __launch_bounds__(256, 2) void k_down(const float* __restrict__ dw /*[E,H,I]*/)
{
    const uint32_t sb = s2u(dynsmem);
    const uint32_t sA = sb;                      // 6 x 128*PB = 61440 (fp16)
    float* Bs = (float*)(dynsmem + 61440);       // [2][128*P] fp32 = 40960

    const int e   = blockIdx.y;
    const int h0  = blockIdx.x * 128;
    const int tid = threadIdx.x;
    const int w   = tid >> 5, lane = tid & 31;
    const int wm  = w >> 1, wn = w & 1;
    const int gr  = lane >> 2, tg = lane & 3;
    const int lrow = lane & 7, lsel = lane >> 3;

    // Preload whole A: [6][128 rows][4 x 16B] fp16 from g_h
    const __half* hsrc = g_h + (size_t)e * CAP * NI;
#pragma unroll
    for (int p = 0; p < 12; p++) {
        int idx = tid + p * 256;                 // 3072
        int kc = idx >> 9, rem = idx & 511, r = rem >> 2, c = rem & 3;
        int rr = r < CAP ? r : CAP - 1;
        cp16s(sA + kc * (128 * PB) + r * PB + c * 16,
              hsrc + (size_t)rr * NI + kc * 32 + c * 8);
    }
    cp_commit();                                 // group: A

    const float* dwe = dw + ((size_t)e * NH + h0) * NI;
    auto loadB = [&](int buf, int kc) {
        const int k0 = kc * 32;
        float* Bb = Bs + buf * 128 * P;
#pragma unroll
        for (int p = 0; p < 4; p++) {            // 128 rows x 8 f4
            int idx = tid + p * 256;
            int r = idx >> 3, c4 = (idx & 7) << 2;
            cp16(Bb + r * P + c4, dwe + (size_t)r * NI + k0 + c4);
        }
        cp_commit();
    };

    // A ldmatrix lane offset (bytes within a chunk-tile), validated in R8
    const uint32_t aoff = (uint32_t)((wm * 32 + lrow + ((lsel & 1) << 3)) * PB + ((lsel >> 1) << 4));

    float acc[2][8][4] = {};

    loadB(0, 0);
    int buf = 0;
    for (int kc = 0; kc < 6; kc++) {
        if (kc + 1 < 6) { loadB(buf ^ 1, kc + 1); cp_wait<1>(); }
        else           { cp_wait<0>(); }
        __syncthreads();

        const uint32_t Ab = sA + kc * (128 * PB);
        const float* B = Bs + buf * 128 * P + wn * 64 * P;

#pragma unroll
        for (int ks = 0; ks < 2; ks++) {
            const uint32_t kb = (uint32_t)(ks * 32);   // 16 halves
            const int c0 = ks * 16 + 2 * tg;
            uint32_t a0[4], a1[4];
            ldm_x4(a0, Ab + aoff + kb);
            ldm_x4(a1, Ab + aoff + 16 * PB + kb);
#pragma unroll
            for (int nt = 0; nt < 8; nt++) {
                uint32_t b[2];
                b[0] = pk(ld2(&B[(nt * 8 + gr) * P + c0    ]));
                b[1] = pk(ld2(&B[(nt * 8 + gr) * P + c0 + 8]));
                mma_f16(acc[0][nt], a0, b);
                mma_f16(acc[1][nt], a1, b);
            }
        }
        __syncthreads();
        buf ^= 1;
    }

    // Epilogue -> g_o (fp16)
#pragma unroll
    for (int mt = 0; mt < 2; mt++) {
#pragma unroll
        for (int half = 0; half < 2; half++) {
            const int r = wm * 32 + mt * 16 + gr + half * 8;
            if (r < CAP) {
                __half* dst = g_o + ((size_t)e * CAP + r) * NH + h0 + wn * 64;
#pragma unroll
                for (int nt = 0; nt < 8; nt++) {
                    *(__half2*)(dst + nt * 8 + 2 * tg) =
                        __floats2half2_rn(acc[mt][nt][half * 2 + 0],
                                          acc[mt][nt][half * 2 + 1]);
                }
            }
        }
    }
}

// ---------------------------------------------------------------------------
// Kernel 3: permute-gather + top-k weighted combine + shared expert
// ---------------------------------------------------------------------------
__global__ __launch_bounds__(256) void k_combine(
    const int*   __restrict__ rei,  // [K*S]
    const float* __restrict__ tw,   // [K,S,1]
    const float* __restrict__ sh,   // [1,S,H]
    float*       __restrict__ out)  // [1,S,H]
{
    const int s = blockIdx.x;
    __shared__ int   rows[NK];
    __shared__ float wts[NK];
    if (threadIdx.x < NK) {
        rows[threadIdx.x] = rei[threadIdx.x * NS + s];
        wts[threadIdx.x]  = tw[threadIdx.x * NS + s];
    }
    __syncthreads();

    for (int h = threadIdx.x * 4; h < NH; h += 256 * 4) {
        float4 a = *(const float4*)(sh + (size_t)s * NH + h);
#pragma unroll
        for (int k = 0; k < NK; k++) {
            const __half* src = g_o + (size_t)rows[k] * NH + h;
            float2 f01 = __half22float2(*(const __half2*)(src));
            float2 f23 = __half22float2(*(const __half2*)(src + 2));
            const float wv = wts[k];
            a.x = fmaf(wv, f01.x, a.x);
            a.y = fmaf(wv, f01.y, a.y);
            a.z = fmaf(wv, f23.x, a.z);
            a.w = fmaf(wv, f23.y, a.w);
        }
        *(float4*)(out + (size_t)s * NH + h) = a;
    }
}

// ---------------------------------------------------------------------------
extern "C" void kernel_launch(void* const* d_in, const int* in_sizes, int n_in,
                              void* d_out, int out_size)
{
    const float* hs  = (const float*)d_in[0];
    const int*   tok = (const int*)  d_in[1];
    const int*   rei = (const int*)  d_in[2];
    const float* tw  = (const float*)d_in[3];
    const float* sh  = (const float*)d_in[4];
    const float* gw  = (const float*)d_in[5];
    const float* uw  = (const float*)d_in[6];
    const float* dw  = (const float*)d_in[7];
    float* out = (float*)d_out;

    const int smem1 = 2 * (128 + 96 + 96) * P * 4;    // 102400 B
    const int smem2 = 6 * 128 * PB + 2 * 128 * P * 4; // 61440 + 40960 = 102400 B
    cudaFuncSetAttribute(k_gateup, cudaFuncAttributeMaxDynamicSharedMemorySize, smem1);
    cudaFuncSetAttribute(k_down,   cudaFuncAttributeMaxDynamicSharedMemorySize, smem2);

    dim3 g1(2, NE);         // 320 blocks
    k_gateup<<<g1, 256, smem1>>>(hs, tok, gw, uw);

    dim3 g2(NH / 128, NE);  // 2560 blocks
    k_down<<<g2, 256, smem2>>>(dw);

    k_combine<<<NS, 256>>>(rei, tw, sh, out);
}